// round 8
// baseline (speedup 1.0000x reference)
#include <cuda_runtime.h>
#include <cuda_fp16.h>
#include <math.h>
#include <stdint.h>

// Problem dims (fixed by the dataset)
#define BSZ 4
#define LSZ 2048
#define DSZ 512
#define MROWS (BSZ * LSZ)   // 8192

// Scan chunking
#define NC 64               // chunks along L
#define LC (LSZ / NC)       // 32 steps per chunk

// GEMM tiling: BK=16, 4-stage cp.async pipeline
#define BM 128
#define BN 128
#define BK16 16
#define NCH 32              // DSZ / BK16

#define ROWB16 48                        // 32B data + 16B pad (conflict-free)
#define MATB16 (BM * ROWB16)             // 6144 B per matrix
#define STG16 (4 * MATB16)               // Ahi|Alo|Whi|Wlo = 24 KB
#define GEMM_SMEM (4 * STG16)            // 4 stages = 96 KB

// Scan staging
#define PST 4                            // timesteps per stage
#define PNS (LC / PST)                   // 8 stages
#define PRING 3
#define PSTW (PST * DSZ * 2)             // words per stage (ang + x) = 4096
#define P1_SMEM (PRING * PSTW * 4)       // 48 KB
#define P2_SMEM (P1_SMEM + LC * DSZ * 4) // + 64 KB h tile = 112 KB

// ---------------------------------------------------------------------------
// Scratch (static device globals; no runtime allocation allowed)
// ---------------------------------------------------------------------------
__device__ float    g_angle[MROWS * DSZ];
__device__ uint32_t g_xh[MROWS * DSZ / 2];   // half2-packed hi of x
__device__ uint32_t g_xl[MROWS * DSZ / 2];   // half2-packed lo of x
__device__ uint32_t g_wh[DSZ * DSZ / 2];
__device__ uint32_t g_wl[DSZ * DSZ / 2];
__device__ float2   g_P[BSZ * NC * DSZ];
__device__ float2   g_E[BSZ * NC * DSZ];

// ---------------------------------------------------------------------------
// helpers (baseline sm_80+ PTX only; harness compiles via compute_100)
// ---------------------------------------------------------------------------
__device__ __forceinline__ uint32_t smem_u32(const void* p) {
    uint32_t a;
    asm("{ .reg .u64 t; cvta.to.shared.u64 t, %1; cvt.u32.u64 %0, t; }" : "=r"(a) : "l"(p));
    return a;
}

__device__ __forceinline__ void split2(float x, float y, uint32_t& hi, uint32_t& lo) {
    __half2 h = __floats2half2_rn(x, y);
    float2 hf = __half22float2(h);
    __half2 l = __floats2half2_rn(x - hf.x, y - hf.y);
    hi = *reinterpret_cast<uint32_t*>(&h);
    lo = *reinterpret_cast<uint32_t*>(&l);
}

__device__ __forceinline__ void mma16(float* d, const uint32_t* a,
                                      uint32_t b0, uint32_t b1) {
    asm volatile(
        "mma.sync.aligned.m16n8k16.row.col.f32.f16.f16.f32 "
        "{%0,%1,%2,%3}, {%4,%5,%6,%7}, {%8,%9}, {%0,%1,%2,%3};"
        : "+f"(d[0]), "+f"(d[1]), "+f"(d[2]), "+f"(d[3])
        : "r"(a[0]), "r"(a[1]), "r"(a[2]), "r"(a[3]), "r"(b0), "r"(b1));
}

__device__ __forceinline__ void ldm4(uint32_t* r, uint32_t addr) {
    asm volatile("ldmatrix.sync.aligned.m8n8.x4.shared.b16 {%0,%1,%2,%3}, [%4];"
        : "=r"(r[0]), "=r"(r[1]), "=r"(r[2]), "=r"(r[3]) : "r"(addr));
}

#define CPA16(dst, src) \
    asm volatile("cp.async.cg.shared.global [%0], [%1], 16;" :: "r"(dst), "l"(src))
#define CPA_COMMIT() asm volatile("cp.async.commit_group;" ::: "memory")
#define CPA_WAIT(n)  asm volatile("cp.async.wait_group %0;" :: "n"(n) : "memory")

// Tail-aware wait: need group `idx` complete given commits stop at `last`.
#define WAIT_PIPE(idx, last) do {                   \
    if ((idx) < (last) - 1)      CPA_WAIT(2);       \
    else if ((idx) == (last) - 1) CPA_WAIT(1);      \
    else                          CPA_WAIT(0);      \
} while (0)

// ---------------------------------------------------------------------------
// Kernel 0: split x and W into packed half2 hi/lo arrays
// ---------------------------------------------------------------------------
#define NX8 (MROWS * DSZ / 8)
#define NW8 (DSZ * DSZ / 8)

__global__ __launch_bounds__(256) void split_kernel(
    const float* __restrict__ x, const float* __restrict__ w)
{
    const int i = blockIdx.x * blockDim.x + threadIdx.x;
    if (i < NX8) {
        const float4* p = (const float4*)x + (size_t)i * 2;
        float4 v0 = p[0], v1 = p[1];
        uint4 H, L;
        split2(v0.x, v0.y, H.x, L.x);
        split2(v0.z, v0.w, H.y, L.y);
        split2(v1.x, v1.y, H.z, L.z);
        split2(v1.z, v1.w, H.w, L.w);
        ((uint4*)g_xh)[i] = H;
        ((uint4*)g_xl)[i] = L;
    } else if (i < NX8 + NW8) {
        const int j = i - NX8;
        const float4* p = (const float4*)w + (size_t)j * 2;
        float4 v0 = p[0], v1 = p[1];
        uint4 H, L;
        split2(v0.x, v0.y, H.x, L.x);
        split2(v0.z, v0.w, H.y, L.y);
        split2(v1.x, v1.y, H.z, L.z);
        split2(v1.z, v1.w, H.w, L.w);
        ((uint4*)g_wh)[j] = H;
        ((uint4*)g_wl)[j] = L;
    }
}

// ---------------------------------------------------------------------------
// GEMM: angle = x @ W^T + b, split-fp16 (hi*hi + hi*lo + lo*hi), mma.sync.
// 4-stage BK=16 cp.async pipeline; 2 CTAs/SM.
// ---------------------------------------------------------------------------
__global__ __launch_bounds__(256, 2) void gemm_mma(const float* __restrict__ bias)
{
    extern __shared__ char dynsm[];
    const uint32_t sb = smem_u32(dynsm);

    const int tid  = threadIdx.x;
    const int wid  = tid >> 5;
    const int lane = tid & 31;
    const int g    = lane >> 2;
    const int tg   = lane & 3;
    const int bm   = blockIdx.y * BM;
    const int bn   = blockIdx.x * BN;
    const int m0w  = (wid >> 1) * 32;
    const int n0w  = (wid & 1) * 64;

    // ldmatrix base addresses (stage offset added per chunk)
    const int lmr = lane & 15;
    const int lmk = (lane >> 4) * 16;
    uint32_t aHi[2], bHi[4];
#pragma unroll
    for (int mt = 0; mt < 2; mt++)
        aHi[mt] = sb + (m0w + mt * 16 + lmr) * ROWB16 + lmk;
#pragma unroll
    for (int p = 0; p < 4; p++)
        bHi[p] = sb + 2 * MATB16 + (n0w + p * 16 + lmr) * ROWB16 + lmk;

    const char* xh = (const char*)g_xh;
    const char* xl = (const char*)g_xl;
    const char* wh = (const char*)g_wh;
    const char* wl = (const char*)g_wl;

    // staging: thread -> (row = tid>>1, 16B half = tid&1)
    const int srow = tid >> 1;
    const int shf  = (tid & 1) * 16;

    auto load_chunk = [&](int c) {
        const uint32_t st = sb + (c & 3) * STG16;
        const int kb = c * 32;   // bytes along K (16 halves * 2B)
        const uint32_t dst = st + srow * ROWB16 + shf;
        const size_t  asrc = (size_t)(bm + srow) * (DSZ * 2) + kb + shf;
        const size_t  wsrc = (size_t)(bn + srow) * (DSZ * 2) + kb + shf;
        CPA16(dst,              xh + asrc);
        CPA16(dst + MATB16,     xl + asrc);
        CPA16(dst + 2 * MATB16, wh + wsrc);
        CPA16(dst + 3 * MATB16, wl + wsrc);
        CPA_COMMIT();
    };

    float C[2][8][4];
#pragma unroll
    for (int mt = 0; mt < 2; mt++)
#pragma unroll
        for (int nt = 0; nt < 8; nt++)
#pragma unroll
            for (int j = 0; j < 4; j++) C[mt][nt][j] = 0.f;

    load_chunk(0);
    load_chunk(1);
    load_chunk(2);

    for (int c = 0; c < NCH; c++) {
        WAIT_PIPE(c, NCH - 1);
        __syncthreads();
        if (c + 3 < NCH) load_chunk(c + 3);

        const uint32_t off = (c & 3) * STG16;
        uint32_t ah[2][4], al[2][4];
#pragma unroll
        for (int mt = 0; mt < 2; mt++) {
            ldm4(ah[mt], aHi[mt] + off);
            ldm4(al[mt], aHi[mt] + off + MATB16);
        }
#pragma unroll
        for (int p = 0; p < 4; p++) {
            uint32_t bh[4], bl[4];
            ldm4(bh, bHi[p] + off);
            ldm4(bl, bHi[p] + off + MATB16);
#pragma unroll
            for (int mt = 0; mt < 2; mt++) {
                mma16(C[mt][2 * p],     ah[mt], bh[0], bh[2]);
                mma16(C[mt][2 * p],     ah[mt], bl[0], bl[2]);
                mma16(C[mt][2 * p],     al[mt], bh[0], bh[2]);
                mma16(C[mt][2 * p + 1], ah[mt], bh[1], bh[3]);
                mma16(C[mt][2 * p + 1], ah[mt], bl[1], bl[3]);
                mma16(C[mt][2 * p + 1], al[mt], bh[1], bh[3]);
            }
        }
    }

    // epilogue: C + bias -> g_angle (float2 stores)
#pragma unroll
    for (int nt = 0; nt < 8; nt++) {
        const int col = bn + n0w + nt * 8 + 2 * tg;
        const float bz0 = bias[col], bz1 = bias[col + 1];
#pragma unroll
        for (int mt = 0; mt < 2; mt++) {
            const int row = bm + m0w + mt * 16 + g;
            float2 v0 = make_float2(C[mt][nt][0] + bz0, C[mt][nt][1] + bz1);
            float2 v1 = make_float2(C[mt][nt][2] + bz0, C[mt][nt][3] + bz1);
            *(float2*)(g_angle + (size_t)row * DSZ + col) = v0;
            *(float2*)(g_angle + (size_t)(row + 8) * DSZ + col) = v1;
        }
    }
}

// ---------------------------------------------------------------------------
// Complex linear scan:  g[t] = c[t]*g[t-1] + x[t], cp.async-staged inputs.
// ---------------------------------------------------------------------------
#define EDECAY 0.999000499833375f   // expf(-0.001f)

__global__ __launch_bounds__(512, 2) void scan_phase1(
    const float* __restrict__ x, const float* __restrict__ scale,
    const float* __restrict__ lre, const float* __restrict__ lim)
{
    extern __shared__ float psm[];
    const uint32_t sbase = smem_u32(psm);

    const int b = blockIdx.x / NC;
    const int c = blockIdx.x % NC;
    const int d = threadIdx.x;
    const size_t gbase = ((size_t)b * LSZ + (size_t)c * LC);
    const float* xp0 = x + gbase * DSZ;
    const float* ap0 = g_angle + gbase * DSZ;

    auto load_stage = [&](int ss) {
        const uint32_t so = sbase + (ss % PRING) * (PSTW * 4);
#pragma unroll
        for (int k = 0; k < 2; k++) {
            const int i = d + k * 512;
            const int rowi = i >> 7, seg = i & 127;
            const float* src = (rowi < 4)
                ? (ap0 + (size_t)(ss * PST + rowi) * DSZ + seg * 4)
                : (xp0 + (size_t)(ss * PST + rowi - 4) * DSZ + seg * 4);
            CPA16(so + rowi * 2048 + seg * 16, src);
        }
        CPA_COMMIT();
    };

    load_stage(0);
    load_stage(1);
    load_stage(2);

    const float sc = scale[d];
    const float lr_ = lre[d], li_ = lim[d];

    float gr = 0.f, gi = 0.f, Pr = 1.f, Pi = 0.f;

    for (int ss = 0; ss < PNS; ss++) {
        WAIT_PIPE(ss, PNS - 1);
        __syncthreads();
        const float* ang = psm + (ss % PRING) * PSTW;
        const float* xx  = ang + PST * DSZ;
#pragma unroll
        for (int st = 0; st < PST; st++) {
            const float a  = ang[st * DSZ + d];
            const float xv = xx[st * DSZ + d];
            float s, co;
            __sincosf(a * sc, &s, &co);
            if (c == 0 && ss == 0 && st == 0) {
                gr = xv + EDECAY * (co * lr_ - s * li_);
                gi = EDECAY * (co * li_ + s * lr_);
            } else {
                const float cr = EDECAY * co, ci = EDECAY * s;
                float ngr = fmaf(cr, gr, fmaf(-ci, gi, xv));
                float ngi = fmaf(cr, gi, ci * gr);
                gr = ngr; gi = ngi;
                float nPr = fmaf(cr, Pr, -ci * Pi);
                float nPi = fmaf(cr, Pi,  ci * Pr);
                Pr = nPr; Pi = nPi;
            }
        }
        __syncthreads();
        if (ss + PRING < PNS) load_stage(ss + PRING);
    }

    const int idx = (b * NC + c) * DSZ + d;
    g_E[idx] = make_float2(gr, gi);
    g_P[idx] = make_float2(Pr, Pi);
}

// Phase 2: staged scan into smem h[LC][DSZ], then per-warp LN rows.
__global__ __launch_bounds__(512, 2) void scan_phase2_ln(
    const float* __restrict__ x, const float* __restrict__ scale,
    const float* __restrict__ lre, const float* __restrict__ lim,
    const float* __restrict__ gamma, const float* __restrict__ beta,
    float* __restrict__ y)
{
    extern __shared__ float psm[];
    const uint32_t sbase = smem_u32(psm);
    float* hsm = psm + PRING * PSTW;   // [LC][DSZ]

    const int b = blockIdx.x / NC;
    const int c = blockIdx.x % NC;
    const int d = threadIdx.x;
    const int lane = d & 31, w = d >> 5;
    const size_t gbase = ((size_t)b * LSZ + (size_t)c * LC);
    const float* xp0 = x + gbase * DSZ;
    const float* ap0 = g_angle + gbase * DSZ;

    auto load_stage = [&](int ss) {
        const uint32_t so = sbase + (ss % PRING) * (PSTW * 4);
#pragma unroll
        for (int k = 0; k < 2; k++) {
            const int i = d + k * 512;
            const int rowi = i >> 7, seg = i & 127;
            const float* src = (rowi < 4)
                ? (ap0 + (size_t)(ss * PST + rowi) * DSZ + seg * 4)
                : (xp0 + (size_t)(ss * PST + rowi - 4) * DSZ + seg * 4);
            CPA16(so + rowi * 2048 + seg * 16, src);
        }
        CPA_COMMIT();
    };

    load_stage(0);
    load_stage(1);
    load_stage(2);

    const float sc = scale[d];
    const float lr_ = lre[d], li_ = lim[d];

    // carry fold overlaps the in-flight prologue loads
    float gr = 0.f, gi = 0.f;
    for (int j = 0; j < c; j++) {
        const int idx = (b * NC + j) * DSZ + d;
        const float2 P = g_P[idx];
        const float2 E = g_E[idx];
        float ngr = fmaf(P.x, gr, fmaf(-P.y, gi, E.x));
        float ngi = fmaf(P.x, gi, fmaf( P.y, gr, E.y));
        gr = ngr; gi = ngi;
    }

    for (int ss = 0; ss < PNS; ss++) {
        WAIT_PIPE(ss, PNS - 1);
        __syncthreads();
        const float* ang = psm + (ss % PRING) * PSTW;
        const float* xx  = ang + PST * DSZ;
#pragma unroll
        for (int st = 0; st < PST; st++) {
            const int tt = ss * PST + st;
            const float a  = ang[st * DSZ + d];
            const float xv = xx[st * DSZ + d];
            float s, co;
            __sincosf(a * sc, &s, &co);
            if (c == 0 && tt == 0) {
                gr = xv + EDECAY * (co * lr_ - s * li_);
                gi = EDECAY * (co * li_ + s * lr_);
            } else {
                const float cr = EDECAY * co, ci = EDECAY * s;
                float ngr = fmaf(cr, gr, fmaf(-ci, gi, xv));
                float ngi = fmaf(cr, gi, ci * gr);
                gr = ngr; gi = ngi;
            }
            hsm[tt * DSZ + d] = gr;
        }
        __syncthreads();
        if (ss + PRING < PNS) load_stage(ss + PRING);
    }
    __syncthreads();

    // LN: warp w handles rows w, w+16; lane owns 4 float4 slots.
    float4 g4[4], b4[4];
#pragma unroll
    for (int j = 0; j < 4; j++) {
        g4[j] = ((const float4*)gamma)[lane + j * 32];
        b4[j] = ((const float4*)beta)[lane + j * 32];
    }
    float* yrowbase = y + gbase * DSZ;

#pragma unroll
    for (int rr = w; rr < LC; rr += 16) {
        const float4* hp = (const float4*)(hsm + rr * DSZ);
        float4 v[4];
        float s = 0.f, ss2 = 0.f;
#pragma unroll
        for (int j = 0; j < 4; j++) {
            v[j] = hp[lane + j * 32];
            s   += v[j].x + v[j].y + v[j].z + v[j].w;
            ss2 += v[j].x * v[j].x + v[j].y * v[j].y
                 + v[j].z * v[j].z + v[j].w * v[j].w;
        }
#pragma unroll
        for (int o = 16; o > 0; o >>= 1) {
            s   += __shfl_xor_sync(0xffffffffu, s,   o);
            ss2 += __shfl_xor_sync(0xffffffffu, ss2, o);
        }
        const float mu   = s * (1.0f / DSZ);
        const float var  = ss2 * (1.0f / DSZ) - mu * mu;
        const float rstd = rsqrtf(var + 1e-5f);

        float4* yp = (float4*)(yrowbase + (size_t)rr * DSZ);
#pragma unroll
        for (int j = 0; j < 4; j++) {
            float4 o;
            o.x = (v[j].x - mu) * rstd * g4[j].x + b4[j].x;
            o.y = (v[j].y - mu) * rstd * g4[j].y + b4[j].y;
            o.z = (v[j].z - mu) * rstd * g4[j].z + b4[j].z;
            o.w = (v[j].w - mu) * rstd * g4[j].w + b4[j].w;
            yp[lane + j * 32] = o;
        }
    }
}

// ---------------------------------------------------------------------------
// Launch
// ---------------------------------------------------------------------------
extern "C" void kernel_launch(void* const* d_in, const int* in_sizes, int n_in,
                              void* d_out, int out_size)
{
    const float* x     = (const float*)d_in[0];
    const float* fc_w  = (const float*)d_in[1];
    const float* fc_b  = (const float*)d_in[2];
    const float* scale = (const float*)d_in[3];
    const float* lre   = (const float*)d_in[4];
    const float* lim   = (const float*)d_in[5];
    const float* gamma = (const float*)d_in[6];
    const float* beta  = (const float*)d_in[7];
    float* y = (float*)d_out;

    cudaFuncSetAttribute(gemm_mma, cudaFuncAttributeMaxDynamicSharedMemorySize,
                         GEMM_SMEM);
    cudaFuncSetAttribute(scan_phase1, cudaFuncAttributeMaxDynamicSharedMemorySize,
                         P1_SMEM);
    cudaFuncSetAttribute(scan_phase2_ln, cudaFuncAttributeMaxDynamicSharedMemorySize,
                         P2_SMEM);

    const int nsplit = (NX8 + NW8 + 255) / 256;
    split_kernel<<<nsplit, 256>>>(x, fc_w);

    dim3 ggrid(DSZ / BN, MROWS / BM);   // (4, 64) = 256 CTAs
    gemm_mma<<<ggrid, 256, GEMM_SMEM>>>(fc_b);

    scan_phase1<<<BSZ * NC, DSZ, P1_SMEM>>>(x, scale, lre, lim);
    scan_phase2_ln<<<BSZ * NC, DSZ, P2_SMEM>>>(x, scale, lre, lim, gamma, beta, y);
}

// round 9
// speedup vs baseline: 1.1864x; 1.1864x over previous
#include <cuda_runtime.h>
#include <cuda_fp16.h>
#include <math.h>
#include <stdint.h>

// Problem dims (fixed by the dataset)
#define BSZ 4
#define LSZ 2048
#define DSZ 512
#define MROWS (BSZ * LSZ)   // 8192

// Scan chunking
#define NC 64               // chunks along L
#define LC (LSZ / NC)       // 32 steps per chunk

// GEMM tiling
#define BM 128
#define BN 128
#define BK 32
#define NCHUNK (DSZ / BK)   // 16

// smem: row = 32 halves (64B data) padded to 80B -> conflict-free ldmatrix
#define ROWW 20                          // words per row
#define ROWB 80
#define MAT_WORDS (BM * ROWW)            // 2560 words = 10KB per matrix
#define MATB (MAT_WORDS * 4)
#define STAGE_WORDS (4 * MAT_WORDS)      // Ahi|Alo|Whi|Wlo = 40KB
#define STAGEB (STAGE_WORDS * 4)
#define GEMM_SMEM (2 * STAGEB)           // double buffered: 80KB

#define SCAN_SMEM (LC * DSZ * 4)         // 64KB h tile for fused LN

// ---------------------------------------------------------------------------
// Scratch (static device globals; no runtime allocation allowed)
// ---------------------------------------------------------------------------
__device__ float  g_angle[MROWS * DSZ];
__device__ float2 g_P[BSZ * NC * DSZ];
__device__ float2 g_E[BSZ * NC * DSZ];

// ---------------------------------------------------------------------------
// helpers (baseline sm_80+ PTX only; harness compiles via compute_100)
// ---------------------------------------------------------------------------
__device__ __forceinline__ uint32_t smem_u32(const void* p) {
    uint32_t a;
    asm("{ .reg .u64 t; cvta.to.shared.u64 t, %1; cvt.u32.u64 %0, t; }" : "=r"(a) : "l"(p));
    return a;
}

__device__ __forceinline__ void split2(float x, float y, uint32_t& hi, uint32_t& lo) {
    __half2 h = __floats2half2_rn(x, y);
    float2 hf = __half22float2(h);
    __half2 l = __floats2half2_rn(x - hf.x, y - hf.y);
    hi = *reinterpret_cast<uint32_t*>(&h);
    lo = *reinterpret_cast<uint32_t*>(&l);
}

__device__ __forceinline__ void mma16(float* d, const uint32_t* a,
                                      uint32_t b0, uint32_t b1) {
    asm volatile(
        "mma.sync.aligned.m16n8k16.row.col.f32.f16.f16.f32 "
        "{%0,%1,%2,%3}, {%4,%5,%6,%7}, {%8,%9}, {%0,%1,%2,%3};"
        : "+f"(d[0]), "+f"(d[1]), "+f"(d[2]), "+f"(d[3])
        : "r"(a[0]), "r"(a[1]), "r"(a[2]), "r"(a[3]), "r"(b0), "r"(b1));
}

__device__ __forceinline__ void ldm4(uint32_t* r, uint32_t addr) {
    asm volatile("ldmatrix.sync.aligned.m8n8.x4.shared.b16 {%0,%1,%2,%3}, [%4];"
        : "=r"(r[0]), "=r"(r[1]), "=r"(r[2]), "=r"(r[3]) : "r"(addr));
}

// ---------------------------------------------------------------------------
// GEMM: angle = x @ W^T + b, split-fp16 (hi*hi + hi*lo + lo*hi), mma.sync.
// 512 threads = 16 warps (4m x 4n), warp tile 32x32 -> C = 32 regs/thread.
// In-kernel split staging; double-buffered smem; one syncthreads per chunk.
// ---------------------------------------------------------------------------
__global__ __launch_bounds__(512, 1) void gemm_mma(
    const float* __restrict__ A, const float* __restrict__ W,
    const float* __restrict__ bias)
{
    extern __shared__ char dynsm[];
    uint32_t* sm = (uint32_t*)dynsm;
    const uint32_t sb = smem_u32(dynsm);

    const int tid  = threadIdx.x;
    const int wid  = tid >> 5;
    const int lane = tid & 31;
    const int g    = lane >> 2;
    const int tg   = lane & 3;
    const int bm   = blockIdx.y * BM;
    const int bn   = blockIdx.x * BN;
    const int m0w  = (wid >> 2) * 32;   // warp m offset (4 rows of warps)
    const int n0w  = (wid & 3) * 32;    // warp n offset (4 cols of warps)

    // ldmatrix addressing: lane -> (row = lane&15, k-half = lane>>4)
    const int lmr = lane & 15;
    const int lmk = (lane >> 4) * 16;   // bytes
    uint32_t aAddr[2], bAddr[2];
#pragma unroll
    for (int mt = 0; mt < 2; mt++)
        aAddr[mt] = sb + (m0w + mt * 16 + lmr) * ROWB + lmk;
#pragma unroll
    for (int p = 0; p < 2; p++)
        bAddr[p] = sb + 2 * MATB + (n0w + p * 16 + lmr) * ROWB + lmk;

    // staging: row = tid>>2 (0..127), quarter = tid&3 (8 floats each)
    const int srow = tid >> 2;
    const int q    = tid & 3;
    const float* Ag = A + (size_t)(bm + srow) * DSZ + q * 8;
    const float* Wg = W + (size_t)(bn + srow) * DSZ + q * 8;

    float4 pa[2], pw[2];
    auto ldg_chunk = [&](int c) {
        const float* ap = Ag + c * BK;
        const float* wp = Wg + c * BK;
        pa[0] = *(const float4*)(ap);
        pa[1] = *(const float4*)(ap + 4);
        pw[0] = *(const float4*)(wp);
        pw[1] = *(const float4*)(wp + 4);
    };
    auto sts_chunk = [&](int buf) {
        uint32_t* st = sm + buf * STAGE_WORDS;
        const int base = srow * ROWW + q * 4;   // word offset, 16B aligned
        uint4 H, L;
        split2(pa[0].x, pa[0].y, H.x, L.x);
        split2(pa[0].z, pa[0].w, H.y, L.y);
        split2(pa[1].x, pa[1].y, H.z, L.z);
        split2(pa[1].z, pa[1].w, H.w, L.w);
        *(uint4*)(st + base)             = H;
        *(uint4*)(st + MAT_WORDS + base) = L;
        split2(pw[0].x, pw[0].y, H.x, L.x);
        split2(pw[0].z, pw[0].w, H.y, L.y);
        split2(pw[1].x, pw[1].y, H.z, L.z);
        split2(pw[1].z, pw[1].w, H.w, L.w);
        *(uint4*)(st + 2 * MAT_WORDS + base) = H;
        *(uint4*)(st + 3 * MAT_WORDS + base) = L;
    };

    float C[2][4][4];
#pragma unroll
    for (int mt = 0; mt < 2; mt++)
#pragma unroll
        for (int nt = 0; nt < 4; nt++)
#pragma unroll
            for (int j = 0; j < 4; j++) C[mt][nt][j] = 0.f;

    ldg_chunk(0);
    for (int c = 0; c < NCHUNK; c++) {
        const int buf = c & 1;
        sts_chunk(buf);
        __syncthreads();
        if (c + 1 < NCHUNK) ldg_chunk(c + 1);

        const uint32_t boff = buf * STAGEB;
#pragma unroll
        for (int ks = 0; ks < 2; ks++) {
            const uint32_t off = boff + ks * 32;   // k16 step = 32 bytes
            uint32_t ah[2][4], al[2][4];
#pragma unroll
            for (int mt = 0; mt < 2; mt++) {
                ldm4(ah[mt], aAddr[mt] + off);
                ldm4(al[mt], aAddr[mt] + off + MATB);
            }
#pragma unroll
            for (int p = 0; p < 2; p++) {
                uint32_t bh[4], bl[4];
                ldm4(bh, bAddr[p] + off);
                ldm4(bl, bAddr[p] + off + MATB);
#pragma unroll
                for (int mt = 0; mt < 2; mt++) {
                    mma16(C[mt][2 * p],     ah[mt], bh[0], bh[2]);
                    mma16(C[mt][2 * p],     ah[mt], bl[0], bl[2]);
                    mma16(C[mt][2 * p],     al[mt], bh[0], bh[2]);
                    mma16(C[mt][2 * p + 1], ah[mt], bh[1], bh[3]);
                    mma16(C[mt][2 * p + 1], ah[mt], bl[1], bl[3]);
                    mma16(C[mt][2 * p + 1], al[mt], bh[1], bh[3]);
                }
            }
        }
    }

    // epilogue: C + bias -> g_angle (float2 stores)
#pragma unroll
    for (int nt = 0; nt < 4; nt++) {
        const int col = bn + n0w + nt * 8 + 2 * tg;
        const float bz0 = bias[col], bz1 = bias[col + 1];
#pragma unroll
        for (int mt = 0; mt < 2; mt++) {
            const int row = bm + m0w + mt * 16 + g;
            float2 v0 = make_float2(C[mt][nt][0] + bz0, C[mt][nt][1] + bz1);
            float2 v1 = make_float2(C[mt][nt][2] + bz0, C[mt][nt][3] + bz1);
            *(float2*)(g_angle + (size_t)row * DSZ + col) = v0;
            *(float2*)(g_angle + (size_t)(row + 8) * DSZ + col) = v1;
        }
    }
}

// ---------------------------------------------------------------------------
// Complex linear scan:  g[t] = c[t]*g[t-1] + x[t]   (R6-proven versions)
// ---------------------------------------------------------------------------
#define EDECAY 0.999000499833375f   // expf(-0.001f)

__global__ __launch_bounds__(512) void scan_phase1(
    const float* __restrict__ x, const float* __restrict__ scale,
    const float* __restrict__ lre, const float* __restrict__ lim)
{
    const int b = blockIdx.x / NC;
    const int c = blockIdx.x % NC;
    const int d = threadIdx.x;

    const float sc = scale[d];
    const size_t base = ((size_t)b * LSZ + (size_t)c * LC) * DSZ + d;
    const float* ap = g_angle + base;
    const float* xp = x + base;

    float gr = 0.f, gi = 0.f, Pr = 1.f, Pi = 0.f;
    int tt = 0;
    if (c == 0) {
        float a0 = ap[0], x0 = xp[0];
        float s0, c0;
        __sincosf(a0 * sc, &s0, &c0);
        const float lr_ = lre[d], li_ = lim[d];
        gr = x0 + EDECAY * (c0 * lr_ - s0 * li_);
        gi = EDECAY * (c0 * li_ + s0 * lr_);
        tt = 1;
    }
    for (; tt < LC; tt++) {
        float a  = ap[(size_t)tt * DSZ];
        float xv = xp[(size_t)tt * DSZ];
        float s, co;
        __sincosf(a * sc, &s, &co);
        const float cr = EDECAY * co, ci = EDECAY * s;
        float ngr = fmaf(cr, gr, fmaf(-ci, gi, xv));
        float ngi = fmaf(cr, gi, ci * gr);
        gr = ngr; gi = ngi;
        float nPr = fmaf(cr, Pr, -ci * Pi);
        float nPi = fmaf(cr, Pi,  ci * Pr);
        Pr = nPr; Pi = nPi;
    }
    const int idx = (b * NC + c) * DSZ + d;
    g_E[idx] = make_float2(gr, gi);
    g_P[idx] = make_float2(Pr, Pi);
}

// Phase 2: barrier-free scan into smem h[LC][DSZ], then per-warp LN rows.
__global__ __launch_bounds__(512) void scan_phase2_ln(
    const float* __restrict__ x, const float* __restrict__ scale,
    const float* __restrict__ lre, const float* __restrict__ lim,
    const float* __restrict__ gamma, const float* __restrict__ beta,
    float* __restrict__ y)
{
    extern __shared__ char dynsm[];
    float* hsm = (float*)dynsm;   // [LC][DSZ]

    const int b = blockIdx.x / NC;
    const int c = blockIdx.x % NC;
    const int d = threadIdx.x;
    const int lane = d & 31, w = d >> 5;

    const float sc = scale[d];

    float gr = 0.f, gi = 0.f;
    for (int j = 0; j < c; j++) {
        const int idx = (b * NC + j) * DSZ + d;
        const float2 P = g_P[idx];
        const float2 E = g_E[idx];
        float ngr = fmaf(P.x, gr, fmaf(-P.y, gi, E.x));
        float ngi = fmaf(P.x, gi, fmaf( P.y, gr, E.y));
        gr = ngr; gi = ngi;
    }

    const size_t base = ((size_t)b * LSZ + (size_t)c * LC) * DSZ + d;
    const float* ap = g_angle + base;
    const float* xp = x + base;

    int tt = 0;
    if (c == 0) {
        float a0 = ap[0], x0 = xp[0];
        float s0, c0;
        __sincosf(a0 * sc, &s0, &c0);
        const float lr_ = lre[d], li_ = lim[d];
        gr = x0 + EDECAY * (c0 * lr_ - s0 * li_);
        gi = EDECAY * (c0 * li_ + s0 * lr_);
        hsm[d] = gr;
        tt = 1;
    }
    for (; tt < LC; tt++) {
        float a  = ap[(size_t)tt * DSZ];
        float xv = xp[(size_t)tt * DSZ];
        float s, co;
        __sincosf(a * sc, &s, &co);
        const float cr = EDECAY * co, ci = EDECAY * s;
        float ngr = fmaf(cr, gr, fmaf(-ci, gi, xv));
        float ngi = fmaf(cr, gi, ci * gr);
        gr = ngr; gi = ngi;
        hsm[tt * DSZ + d] = gr;
    }
    __syncthreads();

    float4 g4[4], b4[4];
#pragma unroll
    for (int j = 0; j < 4; j++) {
        g4[j] = ((const float4*)gamma)[lane + j * 32];
        b4[j] = ((const float4*)beta)[lane + j * 32];
    }
    float* yrowbase = y + ((size_t)b * LSZ + (size_t)c * LC) * DSZ;

#pragma unroll
    for (int rr = w; rr < LC; rr += 16) {
        const float4* hp = (const float4*)(hsm + rr * DSZ);
        float4 v[4];
        float s = 0.f, ss = 0.f;
#pragma unroll
        for (int j = 0; j < 4; j++) {
            v[j] = hp[lane + j * 32];
            s  += v[j].x + v[j].y + v[j].z + v[j].w;
            ss += v[j].x * v[j].x + v[j].y * v[j].y
                + v[j].z * v[j].z + v[j].w * v[j].w;
        }
#pragma unroll
        for (int o = 16; o > 0; o >>= 1) {
            s  += __shfl_xor_sync(0xffffffffu, s,  o);
            ss += __shfl_xor_sync(0xffffffffu, ss, o);
        }
        const float mu   = s * (1.0f / DSZ);
        const float var  = ss * (1.0f / DSZ) - mu * mu;
        const float rstd = rsqrtf(var + 1e-5f);

        float4* yp = (float4*)(yrowbase + (size_t)rr * DSZ);
#pragma unroll
        for (int j = 0; j < 4; j++) {
            float4 o;
            o.x = (v[j].x - mu) * rstd * g4[j].x + b4[j].x;
            o.y = (v[j].y - mu) * rstd * g4[j].y + b4[j].y;
            o.z = (v[j].z - mu) * rstd * g4[j].z + b4[j].z;
            o.w = (v[j].w - mu) * rstd * g4[j].w + b4[j].w;
            yp[lane + j * 32] = o;
        }
    }
}

// ---------------------------------------------------------------------------
// Launch
// ---------------------------------------------------------------------------
extern "C" void kernel_launch(void* const* d_in, const int* in_sizes, int n_in,
                              void* d_out, int out_size)
{
    const float* x     = (const float*)d_in[0];
    const float* fc_w  = (const float*)d_in[1];
    const float* fc_b  = (const float*)d_in[2];
    const float* scale = (const float*)d_in[3];
    const float* lre   = (const float*)d_in[4];
    const float* lim   = (const float*)d_in[5];
    const float* gamma = (const float*)d_in[6];
    const float* beta  = (const float*)d_in[7];
    float* y = (float*)d_out;

    cudaFuncSetAttribute(gemm_mma, cudaFuncAttributeMaxDynamicSharedMemorySize,
                         GEMM_SMEM);
    cudaFuncSetAttribute(scan_phase2_ln, cudaFuncAttributeMaxDynamicSharedMemorySize,
                         SCAN_SMEM);

    dim3 ggrid(DSZ / BN, MROWS / BM);   // (4, 64) = 256 CTAs
    gemm_mma<<<ggrid, 512, GEMM_SMEM>>>(x, fc_w, fc_b);

    scan_phase1<<<BSZ * NC, DSZ>>>(x, scale, lre, lim);
    scan_phase2_ln<<<BSZ * NC, DSZ, SCAN_SMEM>>>(x, scale, lre, lim, gamma, beta, y);
}

// round 11
// speedup vs baseline: 1.2383x; 1.0437x over previous
#include <cuda_runtime.h>
#include <cuda_fp16.h>
#include <math.h>
#include <stdint.h>

// Problem dims (fixed by the dataset)
#define BSZ 4
#define LSZ 2048
#define DSZ 512
#define MROWS (BSZ * LSZ)   // 8192

// Scan chunking
#define NC 64               // chunks along L
#define LC (LSZ / NC)       // 32 steps per chunk

// GEMM tiling
#define BM 128
#define BN 256
#define BK 32
#define NCHUNK (DSZ / BK)   // 16

// smem rows: 32 halves (64B data) padded to 80B -> conflict-free ldmatrix
#define ROWW 20
#define ROWB 80
#define A_MATB (BM * ROWB)               // 10240 B  (A hi or lo)
#define W_MATB (BN * ROWB)               // 20480 B  (W hi or lo)
#define OFF_AHI 0
#define OFF_ALO A_MATB
#define OFF_WHI (2 * A_MATB)
#define OFF_WLO (2 * A_MATB + W_MATB)
#define STAGEB  (2 * A_MATB + 2 * W_MATB)   // 61440 B
#define GEMM_SMEM (2 * STAGEB)              // 122880 B

#define SCAN_SMEM (LC * DSZ * 4)            // 64KB h tile for fused LN

// ---------------------------------------------------------------------------
// Scratch (static device globals; no runtime allocation allowed)
// ---------------------------------------------------------------------------
__device__ float    g_angle[MROWS * DSZ];
__device__ uint32_t g_wh[DSZ * DSZ / 2];   // half2-packed hi of W
__device__ uint32_t g_wl[DSZ * DSZ / 2];   // half2-packed lo of W
__device__ float2   g_P[BSZ * NC * DSZ];
__device__ float2   g_E[BSZ * NC * DSZ];

// ---------------------------------------------------------------------------
// helpers (baseline sm_80+ PTX only; harness compiles via compute_100)
// ---------------------------------------------------------------------------
__device__ __forceinline__ uint32_t smem_u32(const void* p) {
    uint32_t a;
    asm("{ .reg .u64 t; cvta.to.shared.u64 t, %1; cvt.u32.u64 %0, t; }" : "=r"(a) : "l"(p));
    return a;
}

__device__ __forceinline__ void split2(float x, float y, uint32_t& hi, uint32_t& lo) {
    __half2 h = __floats2half2_rn(x, y);
    float2 hf = __half22float2(h);
    __half2 l = __floats2half2_rn(x - hf.x, y - hf.y);
    hi = *reinterpret_cast<uint32_t*>(&h);
    lo = *reinterpret_cast<uint32_t*>(&l);
}

// D += A * B (m16n8k16 fp16, fp32 accum). NOT volatile: pure register op,
// lets ptxas schedule HMMAs and break accumulator RAW chains.
__device__ __forceinline__ void mma16(float* d, const uint32_t* a,
                                      uint32_t b0, uint32_t b1) {
    asm("mma.sync.aligned.m16n8k16.row.col.f32.f16.f16.f32 "
        "{%0,%1,%2,%3}, {%4,%5,%6,%7}, {%8,%9}, {%0,%1,%2,%3};"
        : "+f"(d[0]), "+f"(d[1]), "+f"(d[2]), "+f"(d[3])
        : "r"(a[0]), "r"(a[1]), "r"(a[2]), "r"(a[3]), "r"(b0), "r"(b1));
}

__device__ __forceinline__ void ldm4(uint32_t* r, uint32_t addr) {
    asm volatile("ldmatrix.sync.aligned.m8n8.x4.shared.b16 {%0,%1,%2,%3}, [%4];"
        : "=r"(r[0]), "=r"(r[1]), "=r"(r[2]), "=r"(r[3]) : "r"(addr));
}

#define CPA16(dst, src) \
    asm volatile("cp.async.cg.shared.global [%0], [%1], 16;" :: "r"(dst), "l"(src))
#define CPA_COMMIT() asm volatile("cp.async.commit_group;" ::: "memory")
#define CPA_WAIT0()  asm volatile("cp.async.wait_group 0;" ::: "memory")

// ---------------------------------------------------------------------------
// Kernel 0: split W into packed half2 hi/lo arrays (1 MB; ~1 us)
// ---------------------------------------------------------------------------
#define NW8 (DSZ * DSZ / 8)

__global__ __launch_bounds__(256) void wsplit_kernel(const float* __restrict__ w)
{
    const int j = blockIdx.x * blockDim.x + threadIdx.x;
    if (j < NW8) {
        const float4* p = (const float4*)w + (size_t)j * 2;
        float4 v0 = p[0], v1 = p[1];
        uint4 H, L;
        split2(v0.x, v0.y, H.x, L.x);
        split2(v0.z, v0.w, H.y, L.y);
        split2(v1.x, v1.y, H.z, L.z);
        split2(v1.z, v1.w, H.w, L.w);
        ((uint4*)g_wh)[j] = H;
        ((uint4*)g_wl)[j] = L;
    }
}

// ---------------------------------------------------------------------------
// GEMM: angle = x @ W^T + b, split-fp16 (hi*hi + hi*lo + lo*hi), mma.sync.
// BM=128 x BN=256; 16 warps (4m x 4n), warp tile 32x64 (C = 64 regs).
// A: LDG+split+STS (8 floats/thread). W: cp.async of pre-split halves.
// ---------------------------------------------------------------------------
__global__ __launch_bounds__(512, 1) void gemm_mma(
    const float* __restrict__ A, const float* __restrict__ bias)
{
    extern __shared__ char dynsm[];
    uint32_t* sm = (uint32_t*)dynsm;
    const uint32_t sb = smem_u32(dynsm);

    const int tid  = threadIdx.x;
    const int wid  = tid >> 5;
    const int lane = tid & 31;
    const int g    = lane >> 2;
    const int tg   = lane & 3;
    const int bm   = blockIdx.y * BM;
    const int bn   = blockIdx.x * BN;
    const int m0w  = (wid >> 2) * 32;   // warp m offset
    const int n0w  = (wid & 3) * 64;    // warp n offset

    // ldmatrix addressing
    const int lmr = lane & 15;
    const int lmk = (lane >> 4) * 16;
    uint32_t aAddr[2], bAddr[4];
#pragma unroll
    for (int mt = 0; mt < 2; mt++)
        aAddr[mt] = sb + OFF_AHI + (m0w + mt * 16 + lmr) * ROWB + lmk;
#pragma unroll
    for (int p = 0; p < 4; p++)
        bAddr[p] = sb + OFF_WHI + (n0w + p * 16 + lmr) * ROWB + lmk;

    // A staging: row = tid>>2 (0..127), quarter = tid&3 (8 floats)
    const int srow = tid >> 2;
    const int q    = tid & 3;
    const float* Ag = A + (size_t)(bm + srow) * DSZ + q * 8;

    // W staging via cp.async: 1024 16B-segs per matrix; 2 per thread.
    const char* whp = (const char*)g_wh;
    const char* wlp = (const char*)g_wl;

    float4 pa[2];
    auto ldgA = [&](int c) {
        const float* ap = Ag + c * BK;
        pa[0] = *(const float4*)(ap);
        pa[1] = *(const float4*)(ap + 4);
    };
    auto stsA = [&](int buf) {
        uint32_t* st = sm + (buf * STAGEB) / 4;
        const int base = srow * ROWW + q * 4;
        uint4 H, L;
        split2(pa[0].x, pa[0].y, H.x, L.x);
        split2(pa[0].z, pa[0].w, H.y, L.y);
        split2(pa[1].x, pa[1].y, H.z, L.z);
        split2(pa[1].z, pa[1].w, H.w, L.w);
        *(uint4*)(st + base)               = H;
        *(uint4*)(st + A_MATB / 4 + base)  = L;
    };
    auto cpW = [&](int c, int buf) {
        const uint32_t st = sb + buf * STAGEB;
#pragma unroll
        for (int k = 0; k < 2; k++) {
            const int s   = tid + k * 512;
            const int row = s >> 2, seg = (s & 3) * 16;
            const uint32_t dst = st + row * ROWB + seg;
            const size_t  src = (size_t)(bn + row) * (DSZ * 2) + c * 64 + seg;
            CPA16(dst + OFF_WHI, whp + src);
            CPA16(dst + OFF_WLO, wlp + src);
        }
        CPA_COMMIT();
    };

    float C[2][8][4];
#pragma unroll
    for (int mt = 0; mt < 2; mt++)
#pragma unroll
        for (int nt = 0; nt < 8; nt++)
#pragma unroll
            for (int j = 0; j < 4; j++) C[mt][nt][j] = 0.f;

    ldgA(0);
    cpW(0, 0);

    for (int c = 0; c < NCHUNK; c++) {
        const int buf = c & 1;
        stsA(buf);
        CPA_WAIT0();
        __syncthreads();
        if (c + 1 < NCHUNK) { ldgA(c + 1); cpW(c + 1, buf ^ 1); }

        const uint32_t boff = buf * STAGEB;
#pragma unroll
        for (int ks = 0; ks < 2; ks++) {
            const uint32_t off = boff + ks * 32;
            uint32_t ah[2][4], al[2][4];
#pragma unroll
            for (int mt = 0; mt < 2; mt++) {
                ldm4(ah[mt], aAddr[mt] + off);
                ldm4(al[mt], aAddr[mt] + off + A_MATB);
            }
#pragma unroll
            for (int p = 0; p < 4; p++) {
                uint32_t bh[4], bl[4];
                ldm4(bh, bAddr[p] + off);
                ldm4(bl, bAddr[p] + off + W_MATB);
                // accumulator-major ordering: distance-4 RAW chains
                mma16(C[0][2 * p],     ah[0], bh[0], bh[2]);
                mma16(C[0][2 * p + 1], ah[0], bh[1], bh[3]);
                mma16(C[1][2 * p],     ah[1], bh[0], bh[2]);
                mma16(C[1][2 * p + 1], ah[1], bh[1], bh[3]);
                mma16(C[0][2 * p],     ah[0], bl[0], bl[2]);
                mma16(C[0][2 * p + 1], ah[0], bl[1], bl[3]);
                mma16(C[1][2 * p],     ah[1], bl[0], bl[2]);
                mma16(C[1][2 * p + 1], ah[1], bl[1], bl[3]);
                mma16(C[0][2 * p],     al[0], bh[0], bh[2]);
                mma16(C[0][2 * p + 1], al[0], bh[1], bh[3]);
                mma16(C[1][2 * p],     al[1], bh[0], bh[2]);
                mma16(C[1][2 * p + 1], al[1], bh[1], bh[3]);
            }
        }
    }

    // epilogue: C + bias -> g_angle (float2 stores)
#pragma unroll
    for (int nt = 0; nt < 8; nt++) {
        const int col = bn + n0w + nt * 8 + 2 * tg;
        const float bz0 = bias[col], bz1 = bias[col + 1];
#pragma unroll
        for (int mt = 0; mt < 2; mt++) {
            const int row = bm + m0w + mt * 16 + g;
            float2 v0 = make_float2(C[mt][nt][0] + bz0, C[mt][nt][1] + bz1);
            float2 v1 = make_float2(C[mt][nt][2] + bz0, C[mt][nt][3] + bz1);
            *(float2*)(g_angle + (size_t)row * DSZ + col) = v0;
            *(float2*)(g_angle + (size_t)(row + 8) * DSZ + col) = v1;
        }
    }
}

// ---------------------------------------------------------------------------
// Complex linear scan:  g[t] = c[t]*g[t-1] + x[t]   (R9-proven versions)
// ---------------------------------------------------------------------------
#define EDECAY 0.999000499833375f   // expf(-0.001f)

__global__ __launch_bounds__(512) void scan_phase1(
    const float* __restrict__ x, const float* __restrict__ scale,
    const float* __restrict__ lre, const float* __restrict__ lim)
{
    const int b = blockIdx.x / NC;
    const int c = blockIdx.x % NC;
    const int d = threadIdx.x;

    const float sc = scale[d];
    const size_t base = ((size_t)b * LSZ + (size_t)c * LC) * DSZ + d;
    const float* ap = g_angle + base;
    const float* xp = x + base;

    float gr = 0.f, gi = 0.f, Pr = 1.f, Pi = 0.f;
    int tt = 0;
    if (c == 0) {
        float a0 = ap[0], x0 = xp[0];
        float s0, c0;
        __sincosf(a0 * sc, &s0, &c0);
        const float lr_ = lre[d], li_ = lim[d];
        gr = x0 + EDECAY * (c0 * lr_ - s0 * li_);
        gi = EDECAY * (c0 * li_ + s0 * lr_);
        tt = 1;
    }
    for (; tt < LC; tt++) {
        float a  = ap[(size_t)tt * DSZ];
        float xv = xp[(size_t)tt * DSZ];
        float s, co;
        __sincosf(a * sc, &s, &co);
        const float cr = EDECAY * co, ci = EDECAY * s;
        float ngr = fmaf(cr, gr, fmaf(-ci, gi, xv));
        float ngi = fmaf(cr, gi, ci * gr);
        gr = ngr; gi = ngi;
        float nPr = fmaf(cr, Pr, -ci * Pi);
        float nPi = fmaf(cr, Pi,  ci * Pr);
        Pr = nPr; Pi = nPi;
    }
    const int idx = (b * NC + c) * DSZ + d;
    g_E[idx] = make_float2(gr, gi);
    g_P[idx] = make_float2(Pr, Pi);
}

// Phase 2: barrier-free scan into smem h[LC][DSZ], then per-warp LN rows.
__global__ __launch_bounds__(512) void scan_phase2_ln(
    const float* __restrict__ x, const float* __restrict__ scale,
    const float* __restrict__ lre, const float* __restrict__ lim,
    const float* __restrict__ gamma, const float* __restrict__ beta,
    float* __restrict__ y)
{
    extern __shared__ char dynsm[];
    float* hsm = (float*)dynsm;   // [LC][DSZ]

    const int b = blockIdx.x / NC;
    const int c = blockIdx.x % NC;
    const int d = threadIdx.x;
    const int lane = d & 31, w = d >> 5;

    const float sc = scale[d];

    float gr = 0.f, gi = 0.f;
    for (int j = 0; j < c; j++) {
        const int idx = (b * NC + j) * DSZ + d;
        const float2 P = g_P[idx];
        const float2 E = g_E[idx];
        float ngr = fmaf(P.x, gr, fmaf(-P.y, gi, E.x));
        float ngi = fmaf(P.x, gi, fmaf( P.y, gr, E.y));
        gr = ngr; gi = ngi;
    }

    const size_t base = ((size_t)b * LSZ + (size_t)c * LC) * DSZ + d;
    const float* ap = g_angle + base;
    const float* xp = x + base;

    int tt = 0;
    if (c == 0) {
        float a0 = ap[0], x0 = xp[0];
        float s0, c0;
        __sincosf(a0 * sc, &s0, &c0);
        const float lr_ = lre[d], li_ = lim[d];
        gr = x0 + EDECAY * (c0 * lr_ - s0 * li_);
        gi = EDECAY * (c0 * li_ + s0 * lr_);
        hsm[d] = gr;
        tt = 1;
    }
    for (; tt < LC; tt++) {
        float a  = ap[(size_t)tt * DSZ];
        float xv = xp[(size_t)tt * DSZ];
        float s, co;
        __sincosf(a * sc, &s, &co);
        const float cr = EDECAY * co, ci = EDECAY * s;
        float ngr = fmaf(cr, gr, fmaf(-ci, gi, xv));
        float ngi = fmaf(cr, gi, ci * gr);
        gr = ngr; gi = ngi;
        hsm[tt * DSZ + d] = gr;
    }
    __syncthreads();

    float4 g4[4], b4[4];
#pragma unroll
    for (int j = 0; j < 4; j++) {
        g4[j] = ((const float4*)gamma)[lane + j * 32];
        b4[j] = ((const float4*)beta)[lane + j * 32];
    }
    float* yrowbase = y + ((size_t)b * LSZ + (size_t)c * LC) * DSZ;

#pragma unroll
    for (int rr = w; rr < LC; rr += 16) {
        const float4* hp = (const float4*)(hsm + rr * DSZ);
        float4 v[4];
        float s = 0.f, ss = 0.f;
#pragma unroll
        for (int j = 0; j < 4; j++) {
            v[j] = hp[lane + j * 32];
            s  += v[j].x + v[j].y + v[j].z + v[j].w;
            ss += v[j].x * v[j].x + v[j].y * v[j].y
                + v[j].z * v[j].z + v[j].w * v[j].w;
        }
#pragma unroll
        for (int o = 16; o > 0; o >>= 1) {
            s  += __shfl_xor_sync(0xffffffffu, s,  o);
            ss += __shfl_xor_sync(0xffffffffu, ss, o);
        }
        const float mu   = s * (1.0f / DSZ);
        const float var  = ss * (1.0f / DSZ) - mu * mu;
        const float rstd = rsqrtf(var + 1e-5f);

        float4* yp = (float4*)(yrowbase + (size_t)rr * DSZ);
#pragma unroll
        for (int j = 0; j < 4; j++) {
            float4 o;
            o.x = (v[j].x - mu) * rstd * g4[j].x + b4[j].x;
            o.y = (v[j].y - mu) * rstd * g4[j].y + b4[j].y;
            o.z = (v[j].z - mu) * rstd * g4[j].z + b4[j].z;
            o.w = (v[j].w - mu) * rstd * g4[j].w + b4[j].w;
            yp[lane + j * 32] = o;
        }
    }
}

// ---------------------------------------------------------------------------
// Launch
// ---------------------------------------------------------------------------
extern "C" void kernel_launch(void* const* d_in, const int* in_sizes, int n_in,
                              void* d_out, int out_size)
{
    const float* x     = (const float*)d_in[0];
    const float* fc_w  = (const float*)d_in[1];
    const float* fc_b  = (const float*)d_in[2];
    const float* scale = (const float*)d_in[3];
    const float* lre   = (const float*)d_in[4];
    const float* lim   = (const float*)d_in[5];
    const float* gamma = (const float*)d_in[6];
    const float* beta  = (const float*)d_in[7];
    float* y = (float*)d_out;

    cudaFuncSetAttribute(gemm_mma, cudaFuncAttributeMaxDynamicSharedMemorySize,
                         GEMM_SMEM);
    cudaFuncSetAttribute(scan_phase2_ln, cudaFuncAttributeMaxDynamicSharedMemorySize,
                         SCAN_SMEM);

    wsplit_kernel<<<(NW8 + 255) / 256, 256>>>(fc_w);

    dim3 ggrid(DSZ / BN, MROWS / BM);   // (2, 64) = 128 CTAs
    gemm_mma<<<ggrid, 512, GEMM_SMEM>>>(x, fc_b);

    scan_phase1<<<BSZ * NC, DSZ>>>(x, scale, lre, lim);
    scan_phase2_ln<<<BSZ * NC, DSZ, SCAN_SMEM>>>(x, scale, lre, lim, gamma, beta, y);
}